// round 7
// baseline (speedup 1.0000x reference)
#include <cuda_runtime.h>
#include <cuda_bf16.h>
#include <math.h>

// Problem constants (fixed by setup_inputs)
constexpr int B  = 4;
constexpr int H  = 256;
constexpr int W  = 256;
constexpr int C  = 256;
constexpr int K  = 1024;
constexpr int NP = 25;   // 5x5 window

// Mathematical reduction of the reference (validated R5: rel_err 1.4e-8):
//   Attention messages are broadcast-constant along the window axis n; every
//   consumer applies a softmax over n (shift-invariant) -> both layers and
//   Wq/Wk/Wv/Wo cancel exactly.
//   Output = pos + softmax_n(corr[n]) . offsets, with
//     corr[n] = sum_{g in [256n, 256n+256)} win[g] * s[g & 255]
//   where win[g] (g = ch*25 + i*5 + j) is the channel-scrambled window gather
//   (the reference's reshape quirk) and s[ch] = win[ch*25+12] (window center).
//
//   Key layout insight: thread t's 25 gathered values ARE win[t*25 .. t*25+24],
//   a contiguous g-segment spanning at most 2 bins n. So the dot product needs
//   no win[] in shared memory at all — only s (1 KB) — followed by a small
//   deterministic segmented reduction.
__global__ __launch_bounds__(256, 6)
void fine_match_kernel(const float* __restrict__ T,
                       const float* __restrict__ pos,
                       float* __restrict__ out) {
    __shared__ float s_sm[C];            // 1 KB: center feature vector
    __shared__ float part0[256];         // per-thread partial, bin n0(t)
    __shared__ float part1[256];         // per-thread partial, bin n0(t)+1
    __shared__ float corr_sm[NP];

    const int bk = blockIdx.x;           // 0 .. B*K-1
    const int b  = bk >> 10;             // K = 1024
    const int t  = threadIdx.x;          // channel index in the gather

    const float pr = pos[bk * 2 + 0];
    const float pc = pos[bk * 2 + 1];
    const int r = (int)pr;               // astype(int32) truncation; pos >= 0
    const int c = (int)pc;

    const float* __restrict__ Tb = T + (size_t)b * H * W * C + t;

    // Gather 25 window rows into registers. Each thread loads channel t of
    // each row (coalesced 1024 B rows); 25 independent LDGs -> high MLP.
    float v[NP];
    #pragma unroll
    for (int p = 0; p < NP; ++p) {
        const int i  = p / 5, j = p % 5;
        const int rr = r - 2 + i;
        const int cc = c - 2 + j;
        const bool ok = (rr >= 0) & (rr < H) & (cc >= 0) & (cc < W);
        v[p] = ok ? Tb[(size_t)(rr * W + cc) * C] : 0.0f;
    }
    s_sm[t] = v[12];                     // center pixel, channel t
    __syncthreads();

    // Per-thread partial dot: g = t*25 + p, contributes v[p]*s[g&255] to
    // bin n = g>>8. The segment spans at most 2 bins.
    const int g0 = t * NP;
    const int n0 = g0 >> 8;
    const int gsplit = (n0 + 1) << 8;
    float a0 = 0.0f, a1 = 0.0f;
    #pragma unroll
    for (int p = 0; p < NP; ++p) {
        // lanes read s_sm at stride 25 (odd) -> conflict-free
        const float f = v[p] * s_sm[(g0 + p) & (C - 1)];
        if (g0 + p < gsplit) a0 += f; else a1 += f;
    }
    part0[t] = a0;
    part1[t] = a1;
    __syncthreads();

    // Deterministic segmented reduction: lane n sums the ~12 threads whose
    // g-segment overlaps bin n. Fixed iteration order -> bitwise stable.
    if (t < NP) {
        const int n    = t;
        const int t_lo = (256 * n) / 25;               // == ceil((256n-24)/25)
        const int t_hi = min(255, (256 * n + 255) / 25);
        float acc = 0.0f;
        for (int tt = t_lo; tt <= t_hi; ++tt)
            acc += (((tt * NP) >> 8) == n) ? part0[tt] : part1[tt];
        corr_sm[n] = acc;
    }
    __syncwarp();

    // Softmax over 25 logits + expectation over offsets (warp 0 only).
    if (t < 32) {
        const bool valid = (t < NP);
        float lv = valid ? corr_sm[t] : -INFINITY;
        float m = lv;
        #pragma unroll
        for (int o = 16; o; o >>= 1)
            m = fmaxf(m, __shfl_xor_sync(0xffffffffu, m, o));
        float e = valid ? expf(lv - m) : 0.0f;
        float sum = e;
        #pragma unroll
        for (int o = 16; o; o >>= 1)
            sum += __shfl_xor_sync(0xffffffffu, sum, o);

        // off1d = linspace(-3, 2, 5) = -3 + 1.25*idx (faithful to -w//2 = -3)
        float ox = 0.0f, oy = 0.0f;
        if (valid) {
            ox = -3.0f + 1.25f * (float)(t / 5);
            oy = -3.0f + 1.25f * (float)(t % 5);
        }
        float dx = e * ox;
        float dy = e * oy;
        #pragma unroll
        for (int o = 16; o; o >>= 1) {
            dx += __shfl_xor_sync(0xffffffffu, dx, o);
            dy += __shfl_xor_sync(0xffffffffu, dy, o);
        }
        if (t == 0) {
            const float inv = 1.0f / sum;
            out[bk * 2 + 0] = pr + dx * inv;
            out[bk * 2 + 1] = pc + dy * inv;
        }
    }
}

extern "C" void kernel_launch(void* const* d_in, const int* in_sizes, int n_in,
                              void* d_out, int out_size) {
    // metadata order: source_features, target_features, coarse_positions,
    //                 Wq, Wk, Wv, Wo.
    // source_features and all weight matrices are provably unused (softmax
    // shift-invariance eliminates the attention layers entirely).
    const float* target = (const float*)d_in[1];
    const float* pos    = (const float*)d_in[2];
    float* out          = (float*)d_out;

    const int n_points = in_sizes[2] / 2;   // B*K = 4096 for the pinned shape
    fine_match_kernel<<<n_points, 256>>>(target, pos, out);
}

// round 8
// speedup vs baseline: 1.1011x; 1.1011x over previous
#include <cuda_runtime.h>
#include <cuda_bf16.h>
#include <math.h>
#include <stdint.h>

// Problem constants (fixed by setup_inputs)
constexpr int B  = 4;
constexpr int H  = 256;
constexpr int W  = 256;
constexpr int C  = 256;
constexpr int K  = 1024;
constexpr int NP = 25;   // 5x5 window

// Mathematical reduction of the reference (validated R5/R7: rel_err ~1.5e-8):
//   Attention messages are broadcast-constant along the window axis n; every
//   consumer applies a softmax over n (shift-invariant) -> both layers and
//   Wq/Wk/Wv/Wo cancel exactly.
//   Output = pos + softmax_n(corr[n]) . offsets, with
//     corr[n] = sum_{g in [256n,256n+256)} win[g] * s[g & 255],
//   win[g] (g = ch*25 + p) the channel-scrambled window gather and
//   s[ch] = win_row12[ch] (window center).
//
// R7 lesson: two different SM-side gather implementations both pinned at
// ~23us / ~3.8TB/s with issue 53-69% -> test whether the SM side throttles
// the memory system by moving the gather to TMA (cp.async.bulk): 25 x 1KB
// contiguous, 1024B-aligned rows per block, issued by warp 0 only.

__device__ __forceinline__ uint32_t smem_u32(const void* p) {
    return (uint32_t)__cvta_generic_to_shared(p);
}

__global__ __launch_bounds__(256)
void fine_match_kernel(const float* __restrict__ T,
                       const float* __restrict__ pos,
                       float* __restrict__ out) {
    __shared__ __align__(16) float win[NP][C];   // 25.6 KB, row-major [p][ch]
    __shared__ float part0[256];
    __shared__ float part1[256];
    __shared__ float corr_sm[NP];
    __shared__ __align__(8) uint64_t mbar;

    const int bk = blockIdx.x;           // 0 .. B*K-1
    const int b  = bk >> 10;             // K = 1024
    const int t  = threadIdx.x;

    const float pr = pos[bk * 2 + 0];
    const float pc = pos[bk * 2 + 1];
    const int r = (int)pr;               // astype(int32) truncation; pos >= 0
    const int c = (int)pc;

    const uint32_t mbar_a = smem_u32(&mbar);
    if (t == 0) {
        asm volatile("mbarrier.init.shared.b64 [%0], 1;" :: "r"(mbar_a) : "memory");
    }
    __syncthreads();

    // ---- TMA gather: warp 0 issues 25 x 1KB bulk copies (valid rows only) ----
    const char* __restrict__ Tb = (const char*)(T + (size_t)b * H * W * C);
    if (t < 32) {
        const int p  = t;                             // row index 0..24 (t<25)
        const int i  = p / 5, j = p % 5;
        const int rr = r - 2 + i;
        const int cc = c - 2 + j;
        const bool valid = (t < NP) & (rr >= 0) & (rr < H) & (cc >= 0) & (cc < W);
        const unsigned vmask = __ballot_sync(0xffffffffu, valid);
        if (t == 0) {
            const uint32_t txbytes = (uint32_t)__popc(vmask) * (C * 4);
            asm volatile("mbarrier.arrive.expect_tx.shared.b64 _, [%0], %1;"
                         :: "r"(mbar_a), "r"(txbytes) : "memory");
        }
        __syncwarp();                                  // expect_tx before any copy
        if (valid) {
            const char* src = Tb + ((size_t)rr * W + cc) * (C * 4);
            asm volatile(
                "cp.async.bulk.shared::cta.global.mbarrier::complete_tx::bytes "
                "[%0], [%1], %2, [%3];"
                :: "r"(smem_u32(&win[p][0])), "l"(src), "r"(C * 4), "r"(mbar_a)
                : "memory");
        }
    }

    // ---- Zero out-of-range rows (rare; uniform branch skips interior) ----
    if (r < 2 || r > H - 3 || c < 2 || c > W - 3) {
        #pragma unroll
        for (int p = 0; p < NP; ++p) {
            const int rr = r - 2 + p / 5;
            const int cc = c - 2 + p % 5;
            if (rr < 0 || rr >= H || cc < 0 || cc >= W)
                win[p][t] = 0.0f;
        }
    }
    __syncthreads();                     // zero-stores visible block-wide

    // ---- Wait for TMA completion (acquire orders smem reads after writes) ----
    {
        uint32_t done;
        do {
            asm volatile(
                "{\n\t.reg .pred p;\n\t"
                "mbarrier.try_wait.parity.acquire.cta.shared::cta.b64 p, [%1], %2, 0x989680;\n\t"
                "selp.b32 %0, 1, 0, p;\n\t}"
                : "=r"(done) : "r"(mbar_a), "r"(0u) : "memory");
        } while (!done);
    }

    // ---- Per-thread partial dot (thread t owns channel t of all rows) ----
    // g = t*25 + p; s[g&255] = win[12][(m0+p) wrapped]; bin = g>>8 spans <=2.
    const int g0 = t * NP;
    const int n0 = g0 >> 8;
    const int m0 = g0 & (C - 1);
    const int ps = C - m0;               // wrap point within p-range (may be >24)
    float a0 = 0.0f, a1 = 0.0f;
    #pragma unroll
    for (int p = 0; p < NP; ++p) {
        // win[p][t]: lane-consecutive -> conflict-free.
        // win[12][sidx]: lanes stride 25 (odd) mod 256 -> conflict-free.
        const int sidx = (p < ps) ? (m0 + p) : (m0 + p - C);
        const float f = win[p][t] * win[12][sidx];
        if (p < ps) a0 += f; else a1 += f;
    }
    part0[t] = a0;
    part1[t] = a1;
    __syncthreads();

    // ---- Deterministic segmented reduction over the 25 bins ----
    if (t < NP) {
        const int n    = t;
        const int t_lo = (256 * n) / 25;
        const int t_hi = min(255, (256 * n + 255) / 25);
        float acc = 0.0f;
        for (int tt = t_lo; tt <= t_hi; ++tt)
            acc += (((tt * NP) >> 8) == n) ? part0[tt] : part1[tt];
        corr_sm[n] = acc;
    }
    __syncwarp();

    // ---- Softmax over 25 logits + expectation over offsets (warp 0) ----
    if (t < 32) {
        const bool valid = (t < NP);
        float lv = valid ? corr_sm[t] : -INFINITY;
        float m = lv;
        #pragma unroll
        for (int o = 16; o; o >>= 1)
            m = fmaxf(m, __shfl_xor_sync(0xffffffffu, m, o));
        float e = valid ? expf(lv - m) : 0.0f;
        float sum = e;
        #pragma unroll
        for (int o = 16; o; o >>= 1)
            sum += __shfl_xor_sync(0xffffffffu, sum, o);

        // off1d = linspace(-3, 2, 5) = -3 + 1.25*idx (faithful to -w//2 = -3)
        float ox = 0.0f, oy = 0.0f;
        if (valid) {
            ox = -3.0f + 1.25f * (float)(t / 5);
            oy = -3.0f + 1.25f * (float)(t % 5);
        }
        float dx = e * ox;
        float dy = e * oy;
        #pragma unroll
        for (int o = 16; o; o >>= 1) {
            dx += __shfl_xor_sync(0xffffffffu, dx, o);
            dy += __shfl_xor_sync(0xffffffffu, dy, o);
        }
        if (t == 0) {
            const float inv = 1.0f / sum;
            out[bk * 2 + 0] = pr + dx * inv;
            out[bk * 2 + 1] = pc + dy * inv;
        }
    }
}

extern "C" void kernel_launch(void* const* d_in, const int* in_sizes, int n_in,
                              void* d_out, int out_size) {
    // metadata order: source_features, target_features, coarse_positions,
    //                 Wq, Wk, Wv, Wo.
    // source_features and all weight matrices are provably unused (softmax
    // shift-invariance eliminates the attention layers entirely).
    const float* target = (const float*)d_in[1];
    const float* pos    = (const float*)d_in[2];
    float* out          = (float*)d_out;

    const int n_points = in_sizes[2] / 2;   // B*K = 4096 for the pinned shape
    fine_match_kernel<<<n_points, 256>>>(target, pos, out);
}